// round 7
// baseline (speedup 1.0000x reference)
#include <cuda_runtime.h>
#include <cuda_fp16.h>
#include <cstdint>

#define HW 56
#define HWSQ 3136
#define KTAPS 9
#define KELEM 2304

// Ternary weights as fp16 {-1,0,+1}: layout [chunk 8][tap 9][oc 256][k 32]
__device__ __half g_wB[8 * 9 * 256 * 32];
__device__ float g_alpha[256];

static __device__ __forceinline__ uint32_t smem_u32(const void* p) {
    uint32_t a;
    asm("{ .reg .u64 t; cvta.to.shared.u64 t, %1; cvt.u32.u64 %0, t; }" : "=r"(a) : "l"(p));
    return a;
}

// ---------------- quantization ----------------
__global__ void quant_kernel(const float* __restrict__ w) {
    const int oc = blockIdx.x, tid = threadIdx.x;
    const float* wo = w + (size_t)oc * KELEM;
    __shared__ float red[256];
    float s = 0.f;
    for (int i = tid; i < KELEM; i += 256) s += fabsf(wo[i]);
    red[tid] = s; __syncthreads();
    #pragma unroll
    for (int st = 128; st > 0; st >>= 1) { if (tid < st) red[tid] += red[tid + st]; __syncthreads(); }
    const float delta = 0.7f * red[0] / (float)KELEM;
    __syncthreads();
    float ms = 0.f, cnt = 0.f;
    for (int i = tid; i < KELEM; i += 256) {
        float a = fabsf(wo[i]);
        if (a > delta) { ms += a; cnt += 1.f; }
    }
    red[tid] = ms; __syncthreads();
    #pragma unroll
    for (int st = 128; st > 0; st >>= 1) { if (tid < st) red[tid] += red[tid + st]; __syncthreads(); }
    const float mtot = red[0];
    __syncthreads();
    red[tid] = cnt; __syncthreads();
    #pragma unroll
    for (int st = 128; st > 0; st >>= 1) { if (tid < st) red[tid] += red[tid + st]; __syncthreads(); }
    const float alpha = mtot / fmaxf(red[0], 1.f);
    if (tid == 0) g_alpha[oc] = alpha;

    for (int i = tid; i < KELEM; i += 256) {
        const int ic = i / KTAPS, tap = i - ic * KTAPS;
        const float v = wo[i];
        const float t = (v > delta) ? 1.f : ((v < -delta) ? -1.f : 0.f);
        g_wB[(((size_t)(ic >> 5) * 9 + tap) * 256 + oc) * 32 + (ic & 31)] = __float2half_rn(t);
    }
}

// ---------------- conv via mma.sync (fp16, 64x64 warp tiles) ----------------
// CTA: 128 oc x (4 rows x 64 cols). 8 warps = 2 oc-halves x 4 rows.
// SMEM: XH [6 rows][66 cols][40 k pad] fp16 = 31680 B; A 2 x 10240 @31680
#define SM_XH 0
#define SM_A  31680
#define SM_TOTAL 52160
#define XROWB 80

__global__ __launch_bounds__(256, 1) void conv_mma(
    const float* __restrict__ x, float* __restrict__ out)
{
    extern __shared__ char smem[];
    const uint32_t sb = smem_u32(smem);
    const int tid = threadIdx.x, wid = tid >> 5, lane = tid & 31;
    const int oct = blockIdx.x;          // 0..1 (oc half of 256)
    const int rowbase = blockIdx.y * 4;  // 0..52 step 4
    const int nimg = blockIdx.z;

    const int wm = wid & 1;              // oc 64-half within CTA tile
    const int q  = wid >> 1;             // output row 0..3

    const float* xb = x + (size_t)nimg * 256 * HWSQ;

    float acc[4][8][4];
    #pragma unroll
    for (int a = 0; a < 4; a++)
        #pragma unroll
        for (int b = 0; b < 8; b++)
            #pragma unroll
            for (int e = 0; e < 4; e++) acc[a][b][e] = 0.f;

    // issue A load for iter 0
    {
        const __half* src = g_wB + ((size_t)oct * 128) * 32;
        #pragma unroll
        for (int it = 0; it < 2; it++) {
            const int idx = tid + it * 256;
            const int r = idx >> 2, seg = idx & 3;
            asm volatile("cp.async.cg.shared.global [%0], [%1], 16;"
                         :: "r"(sb + SM_A + (uint32_t)(r * XROWB + seg * 16)),
                            "l"(src + r * 32 + seg * 8) : "memory");
        }
        asm volatile("cp.async.commit_group;" ::: "memory");
    }

    const int j = tid & 63;          // col 0..63
    const int high = tid >> 6;       // 0..3

    for (int i = 0; i < 72; i++) {
        const int c = i / 9, t = i - c * 9;
        const int buf = i & 1;
        const int kh = t / 3, kw = t - kh * 3;

        if (t == 0) {
            // build x tile: rows 0..5 (ih=rowbase-1+row), cols 0..65, k 0..31
            #pragma unroll 4
            for (int s = high; s < 192; s += 4) {
                const int row = s % 6, k = s / 6;
                const int ih = rowbase - 1 + row, iw = j - 1;
                float v = 0.f;
                if ((unsigned)ih < (unsigned)HW && (unsigned)iw < (unsigned)HW)
                    v = xb[(size_t)(c * 32 + k) * HWSQ + ih * HW + iw];
                const uint32_t off = (uint32_t)((row * 66 + j) * 40 + k) * 2;
                *(__half*)(smem + SM_XH + off) = __float2half_rn(v);
            }
            // tail cols 64,65: 2 cols x 6 rows x 32 k = 384 items
            for (int s = tid; s < 384; s += 256) {
                const int col = 64 + (s & 1), rem = s >> 1;
                const int row = rem % 6, k = rem / 6;
                const int ih = rowbase - 1 + row, iw = col - 1;
                float v = 0.f;
                if ((unsigned)ih < (unsigned)HW && (unsigned)iw < (unsigned)HW)
                    v = xb[(size_t)(c * 32 + k) * HWSQ + ih * HW + iw];
                const uint32_t off = (uint32_t)((row * 66 + col) * 40 + k) * 2;
                *(__half*)(smem + SM_XH + off) = __float2half_rn(v);
            }
        }

        asm volatile("cp.async.wait_group 0;" ::: "memory");
        __syncthreads();

        // prefetch next A
        if (i + 1 < 72) {
            const int c2 = (i + 1) / 9, t2 = (i + 1) - c2 * 9;
            const __half* src = g_wB + (((size_t)c2 * 9 + t2) * 256 + oct * 128) * 32;
            const uint32_t abase = sb + SM_A + (uint32_t)((buf ^ 1) * 10240);
            #pragma unroll
            for (int it = 0; it < 2; it++) {
                const int idx = tid + it * 256;
                const int r = idx >> 2, seg = idx & 3;
                asm volatile("cp.async.cg.shared.global [%0], [%1], 16;"
                             :: "r"(abase + (uint32_t)(r * XROWB + seg * 16)),
                                "l"(src + r * 32 + seg * 8) : "memory");
            }
            asm volatile("cp.async.commit_group;" ::: "memory");
        }

        // ---- compute ----
        const uint32_t aB = sb + SM_A + (uint32_t)(buf * 10240)
                          + (uint32_t)((wm * 64 + (lane & 15)) * XROWB + ((lane >> 4) << 4));
        const int pxo = (lane & 7) + ((lane & 16) ? 8 : 0);
        const uint32_t kbo = (lane & 8) ? 16u : 0u;
        const uint32_t bH = sb + SM_XH
                          + (uint32_t)(((q + kh) * 66 + kw + pxo) * XROWB) + kbo;

        #pragma unroll
        for (int ks = 0; ks < 2; ks++) {
            const uint32_t ko = (uint32_t)(ks * 32);
            uint32_t bh[16];
            #pragma unroll
            for (int nb = 0; nb < 4; nb++) {
                asm volatile("ldmatrix.sync.aligned.m8n8.x4.shared.b16 {%0,%1,%2,%3}, [%4];"
                    : "=r"(bh[nb*4]),"=r"(bh[nb*4+1]),"=r"(bh[nb*4+2]),"=r"(bh[nb*4+3])
                    : "r"(bH + ko + (uint32_t)(nb * 16 * XROWB)));
            }
            #pragma unroll
            for (int mf = 0; mf < 4; mf++) {
                uint32_t a0, a1, a2, a3;
                asm volatile("ldmatrix.sync.aligned.m8n8.x4.shared.b16 {%0,%1,%2,%3}, [%4];"
                    : "=r"(a0),"=r"(a1),"=r"(a2),"=r"(a3)
                    : "r"(aB + (uint32_t)(mf * 16 * XROWB) + ko));
                #pragma unroll
                for (int nf = 0; nf < 8; nf++) {
                    const int bi = (nf >> 1) * 4 + (nf & 1) * 2;
                    asm volatile("mma.sync.aligned.m16n8k16.row.col.f32.f16.f16.f32 "
                        "{%0,%1,%2,%3}, {%4,%5,%6,%7}, {%8,%9}, {%0,%1,%2,%3};"
                        : "+f"(acc[mf][nf][0]),"+f"(acc[mf][nf][1]),
                          "+f"(acc[mf][nf][2]),"+f"(acc[mf][nf][3])
                        : "r"(a0),"r"(a1),"r"(a2),"r"(a3), "r"(bh[bi]),"r"(bh[bi+1]));
                }
            }
        }
        __syncthreads();
    }

    // ---- epilogue ----
    const int oh = rowbase + q;
    const int r = lane >> 2, cc = lane & 3;
    #pragma unroll
    for (int mf = 0; mf < 4; mf++) {
        const int oc = oct * 128 + wm * 64 + mf * 16 + r;
        const float al0 = g_alpha[oc];
        const float al1 = g_alpha[oc + 8];
        #pragma unroll
        for (int nf = 0; nf < 8; nf++) {
            const int ow = nf * 8 + cc * 2;
            if (ow < 56) {
                float* d0 = out + ((size_t)(nimg * 256 + oc)) * HWSQ + oh * HW + ow;
                float* d1 = d0 + (size_t)8 * HWSQ;
                *(float2*)d0 = make_float2(acc[mf][nf][0] * al0, acc[mf][nf][1] * al0);
                *(float2*)d1 = make_float2(acc[mf][nf][2] * al1, acc[mf][nf][3] * al1);
            }
        }
    }
}

extern "C" void kernel_launch(void* const* d_in, const int* in_sizes, int n_in,
                              void* d_out, int out_size) {
    const float* x = (const float*)d_in[0];
    const float* w = (const float*)d_in[1];
    float* out = (float*)d_out;

    quant_kernel<<<256, 256>>>(w);

    cudaFuncSetAttribute(conv_mma, cudaFuncAttributeMaxDynamicSharedMemorySize, SM_TOTAL);
    dim3 grid(2, 14, 32);
    conv_mma<<<grid, 256, SM_TOTAL>>>(x, out);

    (void)in_sizes; (void)n_in; (void)out_size;
}

// round 8
// speedup vs baseline: 1.1303x; 1.1303x over previous
#include <cuda_runtime.h>
#include <cuda_fp16.h>
#include <cstdint>

#define HW 56
#define HWSQ 3136
#define KTAPS 9
#define KELEM 2304

// Ternary weights as fp16 {-1,0,+1}: layout [chunk 8][tap 9][oc 256][k 32]
__device__ __half g_wB[8 * 9 * 256 * 32];
__device__ float g_alpha[256];
// x converted to fp16 NHWC: [n][h][w][ic]
__device__ __half g_xh[(size_t)32 * 56 * 56 * 256];

static __device__ __forceinline__ uint32_t smem_u32(const void* p) {
    uint32_t a;
    asm("{ .reg .u64 t; cvta.to.shared.u64 t, %1; cvt.u32.u64 %0, t; }" : "=r"(a) : "l"(p));
    return a;
}

// ---------------- NCHW fp32 -> NHWC fp16 ----------------
__global__ __launch_bounds__(256) void convert_kernel(const float* __restrict__ x) {
    const int nh = blockIdx.x;
    const int n = nh / HW, h = nh - n * HW;
    const int tid = threadIdx.x, wid = tid >> 5, lane = tid & 31;
    __shared__ __half sx[256][57];

    for (int ic = wid; ic < 256; ic += 8) {
        const float* row = x + ((size_t)(n * 256 + ic)) * HWSQ + h * HW;
        sx[ic][lane] = __float2half_rn(row[lane]);
        if (lane < 24) sx[ic][32 + lane] = __float2half_rn(row[32 + lane]);
    }
    __syncthreads();

    __half* dst = g_xh + ((size_t)(n * HW + h)) * HW * 256;
    for (int s = tid; s < HW * 128; s += 256) {
        const int w = s >> 7, icp = s & 127;
        const uint32_t v = (uint32_t)__half_as_ushort(sx[2 * icp][w]) |
                           ((uint32_t)__half_as_ushort(sx[2 * icp + 1][w]) << 16);
        *(uint32_t*)(dst + (size_t)w * 256 + 2 * icp) = v;
    }
}

// ---------------- quantization ----------------
__global__ void quant_kernel(const float* __restrict__ w) {
    const int oc = blockIdx.x, tid = threadIdx.x;
    const float* wo = w + (size_t)oc * KELEM;
    __shared__ float red[256];
    float s = 0.f;
    for (int i = tid; i < KELEM; i += 256) s += fabsf(wo[i]);
    red[tid] = s; __syncthreads();
    #pragma unroll
    for (int st = 128; st > 0; st >>= 1) { if (tid < st) red[tid] += red[tid + st]; __syncthreads(); }
    const float delta = 0.7f * red[0] / (float)KELEM;
    __syncthreads();
    float ms = 0.f, cnt = 0.f;
    for (int i = tid; i < KELEM; i += 256) {
        float a = fabsf(wo[i]);
        if (a > delta) { ms += a; cnt += 1.f; }
    }
    red[tid] = ms; __syncthreads();
    #pragma unroll
    for (int st = 128; st > 0; st >>= 1) { if (tid < st) red[tid] += red[tid + st]; __syncthreads(); }
    const float mtot = red[0];
    __syncthreads();
    red[tid] = cnt; __syncthreads();
    #pragma unroll
    for (int st = 128; st > 0; st >>= 1) { if (tid < st) red[tid] += red[tid + st]; __syncthreads(); }
    const float alpha = mtot / fmaxf(red[0], 1.f);
    if (tid == 0) g_alpha[oc] = alpha;

    for (int i = tid; i < KELEM; i += 256) {
        const int ic = i / KTAPS, tap = i - ic * KTAPS;
        const float v = wo[i];
        const float t = (v > delta) ? 1.f : ((v < -delta) ? -1.f : 0.f);
        g_wB[(((size_t)(ic >> 5) * 9 + tap) * 256 + oc) * 32 + (ic & 31)] = __float2half_rn(t);
    }
}

// ---------------- conv via mma.sync (fp16, cp.async x tiles) ----------------
// CTA: 128 oc x (2 rows x 64 cols). 8 warps = 2 oc-halves x 4 px quarters.
// SMEM: X 2 bufs x [4 rows][66 cols][40 k pad] = 2 x 21120; A 2 x 10240 @42240
#define SM_XH 0
#define XBUF_SZ 21120
#define SM_A  42240
#define SM_TOTAL 62720
#define XROWB 80

__global__ __launch_bounds__(256, 3) void conv_mma(
    const float* __restrict__ x, float* __restrict__ out)
{
    extern __shared__ char smem[];
    const uint32_t sb = smem_u32(smem);
    const int tid = threadIdx.x, wid = tid >> 5, lane = tid & 31;
    const int oct = blockIdx.x;          // oc half of 256
    const int rowbase = blockIdx.y * 2;  // 0..54 step 2
    const int nimg = blockIdx.z;

    const int wm = wid & 1;
    const int q  = wid >> 1;
    const int orow = q >> 1;
    const int c0 = (q & 1) * 32;

    float acc[4][4][4];
    #pragma unroll
    for (int a = 0; a < 4; a++)
        #pragma unroll
        for (int b = 0; b < 4; b++)
            #pragma unroll
            for (int e = 0; e < 4; e++) acc[a][b][e] = 0.f;

    const __half* xpix = g_xh + (size_t)nimg * HWSQ * 256;

    // X chunk loader: 4 rows x 66 cols x 64B (4 x 16B cp.async, zfill OOB)
    auto load_x = [&](int c, int xbuf) {
        const uint32_t dbase = sb + SM_XH + (uint32_t)(xbuf * XBUF_SZ);
        for (int s = tid; s < 1056; s += 256) {
            const int seg = s & 3, pix = s >> 2;
            const int col = pix % 66, row = pix / 66;
            const int ih = rowbase - 1 + row, iw = col - 1;
            const bool ok = (unsigned)ih < (unsigned)HW && (unsigned)iw < (unsigned)HW;
            const uint32_t sz = ok ? 16u : 0u;
            const __half* src = xpix + ((size_t)(ih * HW + iw)) * 256 + c * 32 + seg * 8;
            asm volatile("cp.async.cg.shared.global [%0], [%1], 16, %2;"
                         :: "r"(dbase + (uint32_t)(pix * XROWB + seg * 16)),
                            "l"(src), "r"(sz) : "memory");
        }
    };
    // A tap loader
    auto load_a = [&](int c, int t, int abuf) {
        const __half* src = g_wB + (((size_t)c * 9 + t) * 256 + oct * 128) * 32;
        const uint32_t abase = sb + SM_A + (uint32_t)(abuf * 10240);
        #pragma unroll
        for (int it = 0; it < 2; it++) {
            const int idx = tid + it * 256;
            const int r = idx >> 2, seg = idx & 3;
            asm volatile("cp.async.cg.shared.global [%0], [%1], 16;"
                         :: "r"(abase + (uint32_t)(r * XROWB + seg * 16)),
                            "l"(src + r * 32 + seg * 8) : "memory");
        }
    };

    // prologue: X chunk 0 + A tap (0,0)
    load_x(0, 0);
    load_a(0, 0, 0);
    asm volatile("cp.async.commit_group;" ::: "memory");

    for (int i = 0; i < 72; i++) {
        const int c = i / 9, t = i - c * 9;
        const int xbuf = c & 1, abuf = i & 1;
        const int kh = t / 3, kw = t - kh * 3;

        asm volatile("cp.async.wait_group 0;" ::: "memory");
        __syncthreads();

        // prefetch: next chunk's X at tap 0; next tap's A every iter
        if (t == 0 && c < 7) load_x(c + 1, xbuf ^ 1);
        if (i + 1 < 72) {
            const int i2 = i + 1, c2 = i2 / 9, t2 = i2 - c2 * 9;
            load_a(c2, t2, abuf ^ 1);
        }
        asm volatile("cp.async.commit_group;" ::: "memory");

        // ---- compute ----
        const uint32_t aB = sb + SM_A + (uint32_t)(abuf * 10240)
                          + (uint32_t)((wm * 64 + (lane & 15)) * XROWB + ((lane >> 4) << 4));
        const int pxo = (lane & 7) + ((lane & 16) ? 8 : 0);
        const uint32_t kbo = (lane & 8) ? 16u : 0u;
        const uint32_t bH = sb + SM_XH + (uint32_t)(xbuf * XBUF_SZ)
                          + (uint32_t)(((orow + kh) * 66 + c0 + kw + pxo) * XROWB) + kbo;

        #pragma unroll
        for (int ks = 0; ks < 2; ks++) {
            const uint32_t ko = (uint32_t)(ks * 32);
            uint32_t bh[8];
            asm volatile("ldmatrix.sync.aligned.m8n8.x4.shared.b16 {%0,%1,%2,%3}, [%4];"
                : "=r"(bh[0]),"=r"(bh[1]),"=r"(bh[2]),"=r"(bh[3]) : "r"(bH + ko));
            asm volatile("ldmatrix.sync.aligned.m8n8.x4.shared.b16 {%0,%1,%2,%3}, [%4];"
                : "=r"(bh[4]),"=r"(bh[5]),"=r"(bh[6]),"=r"(bh[7]) : "r"(bH + ko + 16 * XROWB));
            #pragma unroll
            for (int mf = 0; mf < 4; mf++) {
                uint32_t a0, a1, a2, a3;
                asm volatile("ldmatrix.sync.aligned.m8n8.x4.shared.b16 {%0,%1,%2,%3}, [%4];"
                    : "=r"(a0),"=r"(a1),"=r"(a2),"=r"(a3)
                    : "r"(aB + (uint32_t)(mf * 16 * XROWB) + ko));
                #pragma unroll
                for (int nf = 0; nf < 4; nf++) {
                    asm volatile("mma.sync.aligned.m16n8k16.row.col.f32.f16.f16.f32 "
                        "{%0,%1,%2,%3}, {%4,%5,%6,%7}, {%8,%9}, {%0,%1,%2,%3};"
                        : "+f"(acc[mf][nf][0]),"+f"(acc[mf][nf][1]),
                          "+f"(acc[mf][nf][2]),"+f"(acc[mf][nf][3])
                        : "r"(a0),"r"(a1),"r"(a2),"r"(a3), "r"(bh[nf*2]),"r"(bh[nf*2+1]));
                }
            }
        }
        __syncthreads();
    }

    // ---- epilogue ----
    const int oh = rowbase + orow;
    const int r = lane >> 2, cc = lane & 3;
    #pragma unroll
    for (int mf = 0; mf < 4; mf++) {
        const int oc = oct * 128 + wm * 64 + mf * 16 + r;
        const float al0 = g_alpha[oc];
        const float al1 = g_alpha[oc + 8];
        #pragma unroll
        for (int nf = 0; nf < 4; nf++) {
            const int ow = c0 + nf * 8 + cc * 2;
            if (ow < 56) {
                float* d0 = out + ((size_t)(nimg * 256 + oc)) * HWSQ + oh * HW + ow;
                float* d1 = d0 + (size_t)8 * HWSQ;
                *(float2*)d0 = make_float2(acc[mf][nf][0] * al0, acc[mf][nf][1] * al0);
                *(float2*)d1 = make_float2(acc[mf][nf][2] * al1, acc[mf][nf][3] * al1);
            }
        }
    }
    (void)x;
}

extern "C" void kernel_launch(void* const* d_in, const int* in_sizes, int n_in,
                              void* d_out, int out_size) {
    const float* x = (const float*)d_in[0];
    const float* w = (const float*)d_in[1];
    float* out = (float*)d_out;

    convert_kernel<<<32 * HW, 256>>>(x);
    quant_kernel<<<256, 256>>>(w);

    cudaFuncSetAttribute(conv_mma, cudaFuncAttributeMaxDynamicSharedMemorySize, SM_TOTAL);
    dim3 grid(2, 28, 32);
    conv_mma<<<grid, 256, SM_TOTAL>>>(x, out);

    (void)in_sizes; (void)n_in; (void)out_size;
}

// round 9
// speedup vs baseline: 1.1626x; 1.0286x over previous
#include <cuda_runtime.h>
#include <cuda_fp16.h>
#include <cstdint>

#define HW 56
#define HWSQ 3136
#define KTAPS 9
#define KELEM 2304

// Ternary weights as fp16 {-1,0,+1}: layout [chunk 8][tap 9][oc 256][k 32]
__device__ __half g_wB[8 * 9 * 256 * 32];
__device__ float g_alpha[256];
// x converted to fp16 NHWC: [n][h][w][ic]
__device__ __half g_xh[(size_t)32 * 56 * 56 * 256];

static __device__ __forceinline__ uint32_t smem_u32(const void* p) {
    uint32_t a;
    asm("{ .reg .u64 t; cvta.to.shared.u64 t, %1; cvt.u32.u64 %0, t; }" : "=r"(a) : "l"(p));
    return a;
}

// ---------------- NCHW fp32 -> NHWC fp16 ----------------
__global__ __launch_bounds__(256) void convert_kernel(const float* __restrict__ x) {
    const int nh = blockIdx.x;
    const int n = nh / HW, h = nh - n * HW;
    const int tid = threadIdx.x, wid = tid >> 5, lane = tid & 31;
    __shared__ __half sx[256][57];

    for (int ic = wid; ic < 256; ic += 8) {
        const float* row = x + ((size_t)(n * 256 + ic)) * HWSQ + h * HW;
        sx[ic][lane] = __float2half_rn(row[lane]);
        if (lane < 24) sx[ic][32 + lane] = __float2half_rn(row[32 + lane]);
    }
    __syncthreads();

    __half* dst = g_xh + ((size_t)(n * HW + h)) * HW * 256;
    for (int s = tid; s < HW * 128; s += 256) {
        const int w = s >> 7, icp = s & 127;
        const uint32_t v = (uint32_t)__half_as_ushort(sx[2 * icp][w]) |
                           ((uint32_t)__half_as_ushort(sx[2 * icp + 1][w]) << 16);
        *(uint32_t*)(dst + (size_t)w * 256 + 2 * icp) = v;
    }
}

// ---------------- quantization ----------------
__global__ void quant_kernel(const float* __restrict__ w) {
    const int oc = blockIdx.x, tid = threadIdx.x;
    const float* wo = w + (size_t)oc * KELEM;
    __shared__ float red[256];
    float s = 0.f;
    for (int i = tid; i < KELEM; i += 256) s += fabsf(wo[i]);
    red[tid] = s; __syncthreads();
    #pragma unroll
    for (int st = 128; st > 0; st >>= 1) { if (tid < st) red[tid] += red[tid + st]; __syncthreads(); }
    const float delta = 0.7f * red[0] / (float)KELEM;
    __syncthreads();
    float ms = 0.f, cnt = 0.f;
    for (int i = tid; i < KELEM; i += 256) {
        float a = fabsf(wo[i]);
        if (a > delta) { ms += a; cnt += 1.f; }
    }
    red[tid] = ms; __syncthreads();
    #pragma unroll
    for (int st = 128; st > 0; st >>= 1) { if (tid < st) red[tid] += red[tid + st]; __syncthreads(); }
    const float mtot = red[0];
    __syncthreads();
    red[tid] = cnt; __syncthreads();
    #pragma unroll
    for (int st = 128; st > 0; st >>= 1) { if (tid < st) red[tid] += red[tid + st]; __syncthreads(); }
    const float alpha = mtot / fmaxf(red[0], 1.f);
    if (tid == 0) g_alpha[oc] = alpha;

    for (int i = tid; i < KELEM; i += 256) {
        const int ic = i / KTAPS, tap = i - ic * KTAPS;
        const float v = wo[i];
        const float t = (v > delta) ? 1.f : ((v < -delta) ? -1.f : 0.f);
        g_wB[(((size_t)(ic >> 5) * 9 + tap) * 256 + oc) * 32 + (ic & 31)] = __float2half_rn(t);
    }
}

// ---------------- conv via mma.sync (deep pipeline) ----------------
// CTA: 128 oc x (2 rows x 64 cols). 8 warps = 2 oc-halves x 4 px quarters.
// SMEM: X 2 x 21120; A 3 x 10240 @42240. Total 72960 -> 3 CTAs/SM.
#define SM_XH 0
#define XBUF_SZ 21120
#define SM_A  42240
#define SM_TOTAL 72960
#define XROWB 80

__global__ __launch_bounds__(256, 3) void conv_mma(
    const float* __restrict__ x, float* __restrict__ out)
{
    extern __shared__ char smem[];
    const uint32_t sb = smem_u32(smem);
    const int tid = threadIdx.x, wid = tid >> 5, lane = tid & 31;
    const int oct = blockIdx.x;
    const int rowbase = blockIdx.y * 2;
    const int nimg = blockIdx.z;

    const int wm = wid & 1;
    const int q  = wid >> 1;
    const int orow = q >> 1;
    const int c0 = (q & 1) * 32;

    float acc[4][4][4];
    #pragma unroll
    for (int a = 0; a < 4; a++)
        #pragma unroll
        for (int b = 0; b < 4; b++)
            #pragma unroll
            for (int e = 0; e < 4; e++) acc[a][b][e] = 0.f;

    const __half* xpix = g_xh + (size_t)nimg * HWSQ * 256;

    auto load_x = [&](int c, int xbuf) {
        const uint32_t dbase = sb + SM_XH + (uint32_t)(xbuf * XBUF_SZ);
        #pragma unroll
        for (int it = 0; it < 5; it++) {
            const int s = tid + it * 256;
            if (s < 1056) {
                const int seg = s & 3, pix = s >> 2;
                const int col = pix % 66, row = pix / 66;
                const int ih = rowbase - 1 + row, iw = col - 1;
                const bool ok = (unsigned)ih < (unsigned)HW && (unsigned)iw < (unsigned)HW;
                const uint32_t sz = ok ? 16u : 0u;
                const __half* src = xpix + ((size_t)(ih * HW + iw)) * 256 + c * 32 + seg * 8;
                asm volatile("cp.async.cg.shared.global [%0], [%1], 16, %2;"
                             :: "r"(dbase + (uint32_t)(pix * XROWB + seg * 16)),
                                "l"(src), "r"(sz) : "memory");
            }
        }
    };
    auto load_a = [&](int i) {   // i = global iter index of the A tap to load
        const int c = i / 9, t = i - c * 9;
        const __half* src = g_wB + (((size_t)c * 9 + t) * 256 + oct * 128) * 32;
        const uint32_t abase = sb + SM_A + (uint32_t)((i % 3) * 10240);
        #pragma unroll
        for (int it = 0; it < 2; it++) {
            const int idx = tid + it * 256;
            const int r = idx >> 2, seg = idx & 3;
            asm volatile("cp.async.cg.shared.global [%0], [%1], 16;"
                         :: "r"(abase + (uint32_t)(r * XROWB + seg * 16)),
                            "l"(src + r * 32 + seg * 8) : "memory");
        }
    };

    // prologue: G0 = {X0, A0}; G1 = {A1}
    load_x(0, 0);
    load_a(0);
    asm volatile("cp.async.commit_group;" ::: "memory");
    load_a(1);
    asm volatile("cp.async.commit_group;" ::: "memory");

    const int pxo = (lane & 7) + ((lane & 16) ? 8 : 0);
    const uint32_t kbo = (lane & 8) ? 16u : 0u;
    const uint32_t aBl = (uint32_t)((wm * 64 + (lane & 15)) * XROWB + ((lane >> 4) << 4));

    #pragma unroll 1
    for (int c = 0; c < 8; c++) {
        const int xbuf = c & 1;
        #pragma unroll
        for (int t = 0; t < 9; t++) {
            const int i = c * 9 + t;
            const int kh = t / 3, kw = t - kh * 3;

            asm volatile("cp.async.wait_group 1;" ::: "memory");
            __syncthreads();

            // prefetch: A for i+2; X for chunk c+1 at t==0
            if (t == 0 && c < 7) load_x(c + 1, xbuf ^ 1);
            if (i + 2 < 72) load_a(i + 2);
            asm volatile("cp.async.commit_group;" ::: "memory");

            const uint32_t aB = sb + SM_A + (uint32_t)((i % 3) * 10240) + aBl;
            const uint32_t bH = sb + SM_XH + (uint32_t)(xbuf * XBUF_SZ)
                              + (uint32_t)(((orow + kh) * 66 + c0 + kw + pxo) * XROWB) + kbo;

            #pragma unroll
            for (int ks = 0; ks < 2; ks++) {
                const uint32_t ko = (uint32_t)(ks * 32);
                uint32_t bh[8];
                asm volatile("ldmatrix.sync.aligned.m8n8.x4.shared.b16 {%0,%1,%2,%3}, [%4];"
                    : "=r"(bh[0]),"=r"(bh[1]),"=r"(bh[2]),"=r"(bh[3]) : "r"(bH + ko));
                asm volatile("ldmatrix.sync.aligned.m8n8.x4.shared.b16 {%0,%1,%2,%3}, [%4];"
                    : "=r"(bh[4]),"=r"(bh[5]),"=r"(bh[6]),"=r"(bh[7]) : "r"(bH + ko + 16 * XROWB));
                #pragma unroll
                for (int mf = 0; mf < 4; mf++) {
                    uint32_t a0, a1, a2, a3;
                    asm volatile("ldmatrix.sync.aligned.m8n8.x4.shared.b16 {%0,%1,%2,%3}, [%4];"
                        : "=r"(a0),"=r"(a1),"=r"(a2),"=r"(a3)
                        : "r"(aB + (uint32_t)(mf * 16 * XROWB) + ko));
                    #pragma unroll
                    for (int nf = 0; nf < 4; nf++) {
                        asm volatile("mma.sync.aligned.m16n8k16.row.col.f32.f16.f16.f32 "
                            "{%0,%1,%2,%3}, {%4,%5,%6,%7}, {%8,%9}, {%0,%1,%2,%3};"
                            : "+f"(acc[mf][nf][0]),"+f"(acc[mf][nf][1]),
                              "+f"(acc[mf][nf][2]),"+f"(acc[mf][nf][3])
                            : "r"(a0),"r"(a1),"r"(a2),"r"(a3), "r"(bh[nf*2]),"r"(bh[nf*2+1]));
                    }
                }
            }
        }
    }

    // ---- epilogue ----
    const int oh = rowbase + orow;
    const int r = lane >> 2, cc = lane & 3;
    #pragma unroll
    for (int mf = 0; mf < 4; mf++) {
        const int oc = oct * 128 + wm * 64 + mf * 16 + r;
        const float al0 = g_alpha[oc];
        const float al1 = g_alpha[oc + 8];
        #pragma unroll
        for (int nf = 0; nf < 4; nf++) {
            const int ow = c0 + nf * 8 + cc * 2;
            if (ow < 56) {
                float* d0 = out + ((size_t)(nimg * 256 + oc)) * HWSQ + oh * HW + ow;
                float* d1 = d0 + (size_t)8 * HWSQ;
                *(float2*)d0 = make_float2(acc[mf][nf][0] * al0, acc[mf][nf][1] * al0);
                *(float2*)d1 = make_float2(acc[mf][nf][2] * al1, acc[mf][nf][3] * al1);
            }
        }
    }
    (void)x;
}

extern "C" void kernel_launch(void* const* d_in, const int* in_sizes, int n_in,
                              void* d_out, int out_size) {
    const float* x = (const float*)d_in[0];
    const float* w = (const float*)d_in[1];
    float* out = (float*)d_out;

    convert_kernel<<<32 * HW, 256>>>(x);
    quant_kernel<<<256, 256>>>(w);

    cudaFuncSetAttribute(conv_mma, cudaFuncAttributeMaxDynamicSharedMemorySize, SM_TOTAL);
    dim3 grid(2, 28, 32);
    conv_mma<<<grid, 256, SM_TOTAL>>>(x, out);

    (void)in_sizes; (void)n_in; (void)out_size;
}

// round 10
// speedup vs baseline: 2.0561x; 1.7685x over previous
#include <cuda_runtime.h>
#include <cuda_fp16.h>
#include <cstdint>

#define HW 56
#define HWSQ 3136
#define KTAPS 9
#define KELEM 2304

// Ternary weights fp16 {-1,0,+1}, kw folded into K:
// row index R = (c*3 + kh)*256 + oc ; row = 104 halves (96 used) = 13 uint4
__device__ uint4 g_wA4[8 * 3 * 256 * 13];
__device__ float g_alpha[256];
// x as fp16 NHWC [n][h][w][ic]: 32*3136*256 halves = 3211264 uint4
__device__ uint4 g_xh4[(size_t)32 * 3136 * 256 / 8];

static __device__ __forceinline__ uint32_t smem_u32(const void* p) {
    uint32_t a;
    asm("{ .reg .u64 t; cvta.to.shared.u64 t, %1; cvt.u32.u64 %0, t; }" : "=r"(a) : "l"(p));
    return a;
}

// ---------------- NCHW fp32 -> NHWC fp16 ----------------
__global__ __launch_bounds__(256) void convert_kernel(const float* __restrict__ x) {
    const int nh = blockIdx.x;
    const int n = nh / HW, h = nh - n * HW;
    const int tid = threadIdx.x, wid = tid >> 5, lane = tid & 31;
    __shared__ __half sx[256][57];

    for (int ic = wid; ic < 256; ic += 8) {
        const float* row = x + ((size_t)(n * 256 + ic)) * HWSQ + h * HW;
        sx[ic][lane] = __float2half_rn(row[lane]);
        if (lane < 24) sx[ic][32 + lane] = __float2half_rn(row[32 + lane]);
    }
    __syncthreads();

    __half* dst = (__half*)g_xh4 + ((size_t)(n * HW + h)) * HW * 256;
    for (int s = tid; s < HW * 128; s += 256) {
        const int w = s >> 7, icp = s & 127;
        const uint32_t v = (uint32_t)__half_as_ushort(sx[2 * icp][w]) |
                           ((uint32_t)__half_as_ushort(sx[2 * icp + 1][w]) << 16);
        *(uint32_t*)(dst + (size_t)w * 256 + 2 * icp) = v;
    }
}

// ---------------- quantization ----------------
__global__ void quant_kernel(const float* __restrict__ w) {
    const int oc = blockIdx.x, tid = threadIdx.x;
    const float* wo = w + (size_t)oc * KELEM;
    __shared__ float red[256];
    float s = 0.f;
    for (int i = tid; i < KELEM; i += 256) s += fabsf(wo[i]);
    red[tid] = s; __syncthreads();
    #pragma unroll
    for (int st = 128; st > 0; st >>= 1) { if (tid < st) red[tid] += red[tid + st]; __syncthreads(); }
    const float delta = 0.7f * red[0] / (float)KELEM;
    __syncthreads();
    float ms = 0.f, cnt = 0.f;
    for (int i = tid; i < KELEM; i += 256) {
        float a = fabsf(wo[i]);
        if (a > delta) { ms += a; cnt += 1.f; }
    }
    red[tid] = ms; __syncthreads();
    #pragma unroll
    for (int st = 128; st > 0; st >>= 1) { if (tid < st) red[tid] += red[tid + st]; __syncthreads(); }
    const float mtot = red[0];
    __syncthreads();
    red[tid] = cnt; __syncthreads();
    #pragma unroll
    for (int st = 128; st > 0; st >>= 1) { if (tid < st) red[tid] += red[tid + st]; __syncthreads(); }
    const float alpha = mtot / fmaxf(red[0], 1.f);
    if (tid == 0) g_alpha[oc] = alpha;

    __half* wa = (__half*)g_wA4;
    // zero pad halves (k 96..103) once per row group
    for (int r = tid; r < 24; r += 256)
        for (int k = 96; k < 104; k++)
            wa[((size_t)r * 256 + oc) * 104 + k] = __float2half_rn(0.f);

    for (int i = tid; i < KELEM; i += 256) {
        const int ic = i / KTAPS, tap = i - ic * KTAPS;
        const int c = ic >> 5, kh = tap / 3, kw = tap - kh * 3;
        const float v = wo[i];
        const float t = (v > delta) ? 1.f : ((v < -delta) ? -1.f : 0.f);
        const int R = (c * 3 + kh) * 256 + oc;
        wa[(size_t)R * 104 + kw * 32 + (ic & 31)] = __float2half_rn(t);
    }
}

// ---------------- conv: K=96 per iteration, 24 iterations ----------------
// CTA: 128 oc x (2 rows x 64 cols). 8 warps = 2 oc-halves x 4 px quarters.
// SMEM: X [4 rows][66 cols][40k pad] = 21120 ; A 3 stages x 26624 @21120
#define SM_X  0
#define SM_A  21120
#define ASTG  26624
#define SM_TOTAL 100992
#define XROWB 80
#define AROWB 208

__global__ __launch_bounds__(256, 2) void conv_mma(
    const float* __restrict__ x, float* __restrict__ out)
{
    extern __shared__ char smem[];
    const uint32_t sb = smem_u32(smem);
    const int tid = threadIdx.x, wid = tid >> 5, lane = tid & 31;
    const int oct = blockIdx.x;
    const int rowbase = blockIdx.y * 2;
    const int nimg = blockIdx.z;

    const int wm = wid & 1;
    const int q  = wid >> 1;
    const int orow = q >> 1;
    const int c0 = (q & 1) * 32;

    float acc[4][4][4];
    #pragma unroll
    for (int a = 0; a < 4; a++)
        #pragma unroll
        for (int b = 0; b < 4; b++)
            #pragma unroll
            for (int e = 0; e < 4; e++) acc[a][b][e] = 0.f;

    const __half* xpix = (const __half*)g_xh4 + (size_t)nimg * HWSQ * 256;

    auto load_x = [&](int c) {
        #pragma unroll
        for (int it = 0; it < 5; it++) {
            const int s = tid + it * 256;
            if (s < 1056) {
                const int seg = s & 3, pix = s >> 2;
                const int col = pix % 66, row = pix / 66;
                const int ih = rowbase - 1 + row, iw = col - 1;
                const bool ok = (unsigned)ih < (unsigned)HW && (unsigned)iw < (unsigned)HW;
                const uint32_t sz = ok ? 16u : 0u;
                const __half* src = xpix + ((size_t)(ih * HW + iw)) * 256 + c * 32 + seg * 8;
                asm volatile("cp.async.cg.shared.global [%0], [%1], 16, %2;"
                             :: "r"(sb + SM_X + (uint32_t)(pix * XROWB + seg * 16)),
                                "l"(src), "r"(sz) : "memory");
            }
        }
    };
    auto load_a = [&](int c2, int kh2, int stage) {
        const int base_row = (c2 * 3 + kh2) * 256 + oct * 128;
        const uint4* srcb = g_wA4 + (size_t)base_row * 13;
        const uint32_t abase = sb + SM_A + (uint32_t)(stage * ASTG);
        #pragma unroll
        for (int it = 0; it < 7; it++) {
            const int s = tid + it * 256;
            if (s < 1664) {
                const int r = s / 13, seg = s - r * 13;
                asm volatile("cp.async.cg.shared.global [%0], [%1], 16;"
                             :: "r"(abase + (uint32_t)(r * AROWB + seg * 16)),
                                "l"(srcb + r * 13 + seg) : "memory");
            }
        }
    };

    // prologue: G0={X(0), A(0,kh0,st0)}; G1={A(0,kh1,st1)}
    load_x(0);
    load_a(0, 0, 0);
    asm volatile("cp.async.commit_group;" ::: "memory");
    load_a(0, 1, 1);
    asm volatile("cp.async.commit_group;" ::: "memory");

    const int pxo = (lane & 7) + ((lane & 16) ? 8 : 0);
    const uint32_t kbo = (lane & 8) ? 16u : 0u;
    const uint32_t aAl = (uint32_t)((wm * 64 + (lane & 15)) * AROWB + ((lane >> 4) << 4));

    #pragma unroll 1
    for (int c = 0; c < 8; c++) {
        #pragma unroll
        for (int kh = 0; kh < 3; kh++) {
            if (kh == 0) { asm volatile("cp.async.wait_group 0;" ::: "memory"); }
            else         { asm volatile("cp.async.wait_group 1;" ::: "memory"); }
            __syncthreads();

            // prefetch A two iterations ahead (stage (kh+2)%3, compile-time)
            const int i2 = c * 3 + kh + 2;
            if (i2 < 24) {
                const int c2 = i2 / 3, kh2 = i2 - c2 * 3;
                load_a(c2, kh2, (kh + 2) % 3);
            }
            asm volatile("cp.async.commit_group;" ::: "memory");

            const uint32_t aA = sb + SM_A + (uint32_t)(kh * ASTG) + aAl;
            const uint32_t bBase = sb + SM_X
                + (uint32_t)(((orow + kh) * 66 + c0 + pxo) * XROWB) + kbo;

            #pragma unroll
            for (int ksg = 0; ksg < 6; ksg++) {
                const int jj = ksg >> 1, ks = ksg & 1;
                const uint32_t bH = bBase + (uint32_t)(jj * XROWB + ks * 32);
                uint32_t bh[8];
                asm volatile("ldmatrix.sync.aligned.m8n8.x4.shared.b16 {%0,%1,%2,%3}, [%4];"
                    : "=r"(bh[0]),"=r"(bh[1]),"=r"(bh[2]),"=r"(bh[3]) : "r"(bH));
                asm volatile("ldmatrix.sync.aligned.m8n8.x4.shared.b16 {%0,%1,%2,%3}, [%4];"
                    : "=r"(bh[4]),"=r"(bh[5]),"=r"(bh[6]),"=r"(bh[7]) : "r"(bH + 16 * XROWB));
                #pragma unroll
                for (int mf = 0; mf < 4; mf++) {
                    uint32_t a0, a1, a2, a3;
                    asm volatile("ldmatrix.sync.aligned.m8n8.x4.shared.b16 {%0,%1,%2,%3}, [%4];"
                        : "=r"(a0),"=r"(a1),"=r"(a2),"=r"(a3)
                        : "r"(aA + (uint32_t)(mf * 16 * AROWB + ksg * 32)));
                    #pragma unroll
                    for (int nf = 0; nf < 4; nf++) {
                        asm volatile("mma.sync.aligned.m16n8k16.row.col.f32.f16.f16.f32 "
                            "{%0,%1,%2,%3}, {%4,%5,%6,%7}, {%8,%9}, {%0,%1,%2,%3};"
                            : "+f"(acc[mf][nf][0]),"+f"(acc[mf][nf][1]),
                              "+f"(acc[mf][nf][2]),"+f"(acc[mf][nf][3])
                            : "r"(a0),"r"(a1),"r"(a2),"r"(a3), "r"(bh[nf*2]),"r"(bh[nf*2+1]));
                    }
                }
            }

            // chunk boundary: rebuild X after all reads of X(c) are done
            if (kh == 2 && c < 7) {
                __syncthreads();
                load_x(c + 1);
                asm volatile("cp.async.commit_group;" ::: "memory");
            }
        }
    }

    // ---- epilogue ----
    const int oh = rowbase + orow;
    const int r = lane >> 2, cc = lane & 3;
    #pragma unroll
    for (int mf = 0; mf < 4; mf++) {
        const int oc = oct * 128 + wm * 64 + mf * 16 + r;
        const float al0 = g_alpha[oc];
        const float al1 = g_alpha[oc + 8];
        #pragma unroll
        for (int nf = 0; nf < 4; nf++) {
            const int ow = c0 + nf * 8 + cc * 2;
            if (ow < 56) {
                float* d0 = out + ((size_t)(nimg * 256 + oc)) * HWSQ + oh * HW + ow;
                float* d1 = d0 + (size_t)8 * HWSQ;
                *(float2*)d0 = make_float2(acc[mf][nf][0] * al0, acc[mf][nf][1] * al0);
                *(float2*)d1 = make_float2(acc[mf][nf][2] * al1, acc[mf][nf][3] * al1);
            }
        }
    }
    (void)x;
}

extern "C" void kernel_launch(void* const* d_in, const int* in_sizes, int n_in,
                              void* d_out, int out_size) {
    const float* x = (const float*)d_in[0];
    const float* w = (const float*)d_in[1];
    float* out = (float*)d_out;

    convert_kernel<<<32 * HW, 256>>>(x);
    quant_kernel<<<256, 256>>>(w);

    cudaFuncSetAttribute(conv_mma, cudaFuncAttributeMaxDynamicSharedMemorySize, SM_TOTAL);
    dim3 grid(2, 28, 32);
    conv_mma<<<grid, 256, SM_TOTAL>>>(x, out);

    (void)in_sizes; (void)n_in; (void)out_size;
}

// round 11
// speedup vs baseline: 2.0765x; 1.0099x over previous
#include <cuda_runtime.h>
#include <cuda_fp16.h>
#include <cstdint>

#define HW 56
#define HWSQ 3136
#define KTAPS 9
#define KELEM 2304

// Ternary weights fp16 {-1,0,+1}, kw folded into K:
// row index R = (c*3 + kh)*256 + oc ; row = 104 halves (96 used) = 13 uint4
__device__ uint4 g_wA4[8 * 3 * 256 * 13];
__device__ float g_alpha[256];
// x as fp16 NHWC [n][h][w][ic]
__device__ uint4 g_xh4[(size_t)32 * 3136 * 256 / 8];

static __device__ __forceinline__ uint32_t smem_u32(const void* p) {
    uint32_t a;
    asm("{ .reg .u64 t; cvta.to.shared.u64 t, %1; cvt.u32.u64 %0, t; }" : "=r"(a) : "l"(p));
    return a;
}

// ---------------- NCHW fp32 -> NHWC fp16 ----------------
__global__ __launch_bounds__(256) void convert_kernel(const float* __restrict__ x) {
    const int nh = blockIdx.x;
    const int n = nh / HW, h = nh - n * HW;
    const int tid = threadIdx.x, wid = tid >> 5, lane = tid & 31;
    __shared__ __half sx[256][57];

    for (int ic = wid; ic < 256; ic += 8) {
        const float* row = x + ((size_t)(n * 256 + ic)) * HWSQ + h * HW;
        sx[ic][lane] = __float2half_rn(row[lane]);
        if (lane < 24) sx[ic][32 + lane] = __float2half_rn(row[32 + lane]);
    }
    __syncthreads();

    __half* dst = (__half*)g_xh4 + ((size_t)(n * HW + h)) * HW * 256;
    for (int s = tid; s < HW * 128; s += 256) {
        const int w = s >> 7, icp = s & 127;
        const uint32_t v = (uint32_t)__half_as_ushort(sx[2 * icp][w]) |
                           ((uint32_t)__half_as_ushort(sx[2 * icp + 1][w]) << 16);
        *(uint32_t*)(dst + (size_t)w * 256 + 2 * icp) = v;
    }
}

// ---------------- quantization ----------------
__global__ void quant_kernel(const float* __restrict__ w) {
    const int oc = blockIdx.x, tid = threadIdx.x;
    const float* wo = w + (size_t)oc * KELEM;
    __shared__ float red[256];
    float s = 0.f;
    for (int i = tid; i < KELEM; i += 256) s += fabsf(wo[i]);
    red[tid] = s; __syncthreads();
    #pragma unroll
    for (int st = 128; st > 0; st >>= 1) { if (tid < st) red[tid] += red[tid + st]; __syncthreads(); }
    const float delta = 0.7f * red[0] / (float)KELEM;
    __syncthreads();
    float ms = 0.f, cnt = 0.f;
    for (int i = tid; i < KELEM; i += 256) {
        float a = fabsf(wo[i]);
        if (a > delta) { ms += a; cnt += 1.f; }
    }
    red[tid] = ms; __syncthreads();
    #pragma unroll
    for (int st = 128; st > 0; st >>= 1) { if (tid < st) red[tid] += red[tid + st]; __syncthreads(); }
    const float mtot = red[0];
    __syncthreads();
    red[tid] = cnt; __syncthreads();
    #pragma unroll
    for (int st = 128; st > 0; st >>= 1) { if (tid < st) red[tid] += red[tid + st]; __syncthreads(); }
    const float alpha = mtot / fmaxf(red[0], 1.f);
    if (tid == 0) g_alpha[oc] = alpha;

    __half* wa = (__half*)g_wA4;
    for (int r = tid; r < 24; r += 256)
        for (int k = 96; k < 104; k++)
            wa[((size_t)r * 256 + oc) * 104 + k] = __float2half_rn(0.f);

    for (int i = tid; i < KELEM; i += 256) {
        const int ic = i / KTAPS, tap = i - ic * KTAPS;
        const int c = ic >> 5, kh = tap / 3, kw = tap - kh * 3;
        const float v = wo[i];
        const float t = (v > delta) ? 1.f : ((v < -delta) ? -1.f : 0.f);
        const int R = (c * 3 + kh) * 256 + oc;
        wa[(size_t)R * 104 + kw * 32 + (ic & 31)] = __float2half_rn(t);
    }
}

// ---------------- conv: K=96/iter, X + A both double-buffered ----------------
// CTA: 128 oc x (2 rows x 64 cols). 8 warps = 2 oc-halves x 4 px quarters.
// SMEM: X 2 x 21120 @0 ; A 2 x 26624 @42240. Total 95488 -> 2 CTAs/SM.
#define SM_X  0
#define XBUF_SZ 21120
#define SM_A  42240
#define ASTG  26624
#define SM_TOTAL 95488
#define XROWB 80
#define AROWB 208

__global__ __launch_bounds__(256, 2) void conv_mma(
    const float* __restrict__ x, float* __restrict__ out)
{
    extern __shared__ char smem[];
    const uint32_t sb = smem_u32(smem);
    const int tid = threadIdx.x, wid = tid >> 5, lane = tid & 31;
    const int oct = blockIdx.x;
    const int rowbase = blockIdx.y * 2;
    const int nimg = blockIdx.z;

    const int wm = wid & 1;
    const int q  = wid >> 1;
    const int orow = q >> 1;
    const int c0 = (q & 1) * 32;

    float acc[4][4][4];
    #pragma unroll
    for (int a = 0; a < 4; a++)
        #pragma unroll
        for (int b = 0; b < 4; b++)
            #pragma unroll
            for (int e = 0; e < 4; e++) acc[a][b][e] = 0.f;

    const __half* xpix = (const __half*)g_xh4 + (size_t)nimg * HWSQ * 256;

    auto load_x = [&](int c, int xbuf) {
        const uint32_t dbase = sb + SM_X + (uint32_t)(xbuf * XBUF_SZ);
        #pragma unroll
        for (int it = 0; it < 5; it++) {
            const int s = tid + it * 256;
            if (s < 1056) {
                const int seg = s & 3, pix = s >> 2;
                const int col = pix % 66, row = pix / 66;
                const int ih = rowbase - 1 + row, iw = col - 1;
                const bool ok = (unsigned)ih < (unsigned)HW && (unsigned)iw < (unsigned)HW;
                const uint32_t sz = ok ? 16u : 0u;
                const __half* src = xpix + ((size_t)(ih * HW + iw)) * 256 + c * 32 + seg * 8;
                asm volatile("cp.async.cg.shared.global [%0], [%1], 16, %2;"
                             :: "r"(dbase + (uint32_t)(pix * XROWB + seg * 16)),
                                "l"(src), "r"(sz) : "memory");
            }
        }
    };
    auto load_a = [&](int i) {   // A for global iter i into stage i&1
        const int c2 = i / 3, kh2 = i - c2 * 3;
        const int base_row = (c2 * 3 + kh2) * 256 + oct * 128;
        const uint4* srcb = g_wA4 + (size_t)base_row * 13;
        const uint32_t abase = sb + SM_A + (uint32_t)((i & 1) * ASTG);
        #pragma unroll
        for (int it = 0; it < 7; it++) {
            const int s = tid + it * 256;
            if (s < 1664) {
                const int r = s / 13, seg = s - r * 13;
                asm volatile("cp.async.cg.shared.global [%0], [%1], 16;"
                             :: "r"(abase + (uint32_t)(r * AROWB + seg * 16)),
                                "l"(srcb + r * 13 + seg) : "memory");
            }
        }
    };

    // prologue: G0 = {X0, A0}
    load_x(0, 0);
    load_a(0);
    asm volatile("cp.async.commit_group;" ::: "memory");

    const int pxo = (lane & 7) + ((lane & 16) ? 8 : 0);
    const uint32_t kbo = (lane & 8) ? 16u : 0u;
    const uint32_t aAl = (uint32_t)((wm * 64 + (lane & 15)) * AROWB + ((lane >> 4) << 4));

    #pragma unroll 1
    for (int c = 0; c < 8; c++) {
        const int xbuf = c & 1;
        #pragma unroll
        for (int kh = 0; kh < 3; kh++) {
            const int i = c * 3 + kh;

            asm volatile("cp.async.wait_group 0;" ::: "memory");
            __syncthreads();

            // prefetch next operands (safe: all prior reads retired by barrier)
            if (kh == 0 && c < 7) load_x(c + 1, xbuf ^ 1);
            if (i + 1 < 24) load_a(i + 1);
            asm volatile("cp.async.commit_group;" ::: "memory");

            const uint32_t aA = sb + SM_A + (uint32_t)((i & 1) * ASTG) + aAl;
            const uint32_t bBase = sb + SM_X + (uint32_t)(xbuf * XBUF_SZ)
                + (uint32_t)(((orow + kh) * 66 + c0 + pxo) * XROWB) + kbo;

            #pragma unroll
            for (int ksg = 0; ksg < 6; ksg++) {
                const int jj = ksg >> 1, ks = ksg & 1;
                const uint32_t bH = bBase + (uint32_t)(jj * XROWB + ks * 32);
                uint32_t bh[8];
                asm volatile("ldmatrix.sync.aligned.m8n8.x4.shared.b16 {%0,%1,%2,%3}, [%4];"
                    : "=r"(bh[0]),"=r"(bh[1]),"=r"(bh[2]),"=r"(bh[3]) : "r"(bH));
                asm volatile("ldmatrix.sync.aligned.m8n8.x4.shared.b16 {%0,%1,%2,%3}, [%4];"
                    : "=r"(bh[4]),"=r"(bh[5]),"=r"(bh[6]),"=r"(bh[7]) : "r"(bH + 16 * XROWB));
                #pragma unroll
                for (int mf = 0; mf < 4; mf++) {
                    uint32_t a0, a1, a2, a3;
                    asm volatile("ldmatrix.sync.aligned.m8n8.x4.shared.b16 {%0,%1,%2,%3}, [%4];"
                        : "=r"(a0),"=r"(a1),"=r"(a2),"=r"(a3)
                        : "r"(aA + (uint32_t)(mf * 16 * AROWB + ksg * 32)));
                    #pragma unroll
                    for (int nf = 0; nf < 4; nf++) {
                        asm volatile("mma.sync.aligned.m16n8k16.row.col.f32.f16.f16.f32 "
                            "{%0,%1,%2,%3}, {%4,%5,%6,%7}, {%8,%9}, {%0,%1,%2,%3};"
                            : "+f"(acc[mf][nf][0]),"+f"(acc[mf][nf][1]),
                              "+f"(acc[mf][nf][2]),"+f"(acc[mf][nf][3])
                            : "r"(a0),"r"(a1),"r"(a2),"r"(a3), "r"(bh[nf*2]),"r"(bh[nf*2+1]));
                    }
                }
            }
        }
    }

    // ---- epilogue ----
    const int oh = rowbase + orow;
    const int r = lane >> 2, cc = lane & 3;
    #pragma unroll
    for (int mf = 0; mf < 4; mf++) {
        const int oc = oct * 128 + wm * 64 + mf * 16 + r;
        const float al0 = g_alpha[oc];
        const float al1 = g_alpha[oc + 8];
        #pragma unroll
        for (int nf = 0; nf < 4; nf++) {
            const int ow = c0 + nf * 8 + cc * 2;
            if (ow < 56) {
                float* d0 = out + ((size_t)(nimg * 256 + oc)) * HWSQ + oh * HW + ow;
                float* d1 = d0 + (size_t)8 * HWSQ;
                *(float2*)d0 = make_float2(acc[mf][nf][0] * al0, acc[mf][nf][1] * al0);
                *(float2*)d1 = make_float2(acc[mf][nf][2] * al1, acc[mf][nf][3] * al1);
            }
        }
    }
    (void)x;
}

extern "C" void kernel_launch(void* const* d_in, const int* in_sizes, int n_in,
                              void* d_out, int out_size) {
    const float* x = (const float*)d_in[0];
    const float* w = (const float*)d_in[1];
    float* out = (float*)d_out;

    convert_kernel<<<32 * HW, 256>>>(x);
    quant_kernel<<<256, 256>>>(w);

    cudaFuncSetAttribute(conv_mma, cudaFuncAttributeMaxDynamicSharedMemorySize, SM_TOTAL);
    dim3 grid(2, 28, 32);
    conv_mma<<<grid, 256, SM_TOTAL>>>(x, out);

    (void)in_sizes; (void)n_in; (void)out_size;
}